// round 3
// baseline (speedup 1.0000x reference)
#include <cuda_runtime.h>
#include <math.h>

// ---------------------------------------------------------------------------
// Scratch (allocation-free rule: __device__ globals)
// ---------------------------------------------------------------------------
#define MAXN        131072
#define EDGE_BLOCKS 1184      // 148 SMs x 8 blocks of 256 = one persistent wave
#define NODE_BLOCKS 160

__device__ float        g_in_sums[MAXN];
__device__ float        g_out_sums[MAXN];
__device__ float        g_edge_partial[EDGE_BLOCKS];     // focal partial per block
__device__ double       g_node_partial[NODE_BLOCKS * 5]; // cov,tour,dem,sq,cnt
__device__ unsigned int g_done;
__device__ int          g_idx64;

// ---------------------------------------------------------------------------
// Kernel 1: zero scratch + detect index dtype + reset done-counter.
// int64 indices < 2^31 have zero high words; int32 buffer has random
// indices there (P[32 zeros] ~ 1e-160).
// ---------------------------------------------------------------------------
__global__ void zero_kernel(const int* __restrict__ ei, int n4) {
    int i = blockIdx.x * blockDim.x + threadIdx.x;
    if (i < n4) {
        reinterpret_cast<float4*>(g_in_sums)[i]  = make_float4(0.f, 0.f, 0.f, 0.f);
        reinterpret_cast<float4*>(g_out_sums)[i] = make_float4(0.f, 0.f, 0.f, 0.f);
    }
    if (blockIdx.x == 0 && threadIdx.x == 0) {
        g_done = 0u;
        int all_hi_zero = 1;
        #pragma unroll
        for (int k = 0; k < 32; k++)
            if (ei[2 * k + 1] != 0) { all_hi_zero = 0; break; }
        g_idx64 = all_hi_zero;
    }
}

// ---------------------------------------------------------------------------
// Block reductions (warp shuffle + shared)
// ---------------------------------------------------------------------------
__device__ __forceinline__ float block_reduce_sum(float v, float* sh) {
    const int lane = threadIdx.x & 31;
    const int wid  = threadIdx.x >> 5;
    #pragma unroll
    for (int o = 16; o > 0; o >>= 1) v += __shfl_down_sync(0xffffffffu, v, o);
    if (lane == 0) sh[wid] = v;
    __syncthreads();
    v = (threadIdx.x < (blockDim.x >> 5)) ? sh[threadIdx.x] : 0.0f;
    if (wid == 0) {
        #pragma unroll
        for (int o = 16; o > 0; o >>= 1) v += __shfl_down_sync(0xffffffffu, v, o);
    }
    __syncthreads();
    return v;   // valid in thread 0
}

__device__ __forceinline__ double block_reduce_sum_d(double v, double* sh) {
    const int lane = threadIdx.x & 31;
    const int wid  = threadIdx.x >> 5;
    #pragma unroll
    for (int o = 16; o > 0; o >>= 1) v += __shfl_down_sync(0xffffffffu, v, o);
    if (lane == 0) sh[wid] = v;
    __syncthreads();
    v = (threadIdx.x < (blockDim.x >> 5)) ? sh[threadIdx.x] : 0.0;
    if (wid == 0) {
        #pragma unroll
        for (int o = 16; o > 0; o >>= 1) v += __shfl_down_sync(0xffffffffu, v, o);
    }
    __syncthreads();
    return v;   // valid in thread 0
}

// ---------------------------------------------------------------------------
// Kernel 2: edge pass
//   p = sigmoid(l) scattered into in/out segment sums (2 float REDG / edge)
//   focal loss partial -> per-block plain store (NO same-address atomics)
//   z = exp(-|l|); p = (l>=0) ? 1/(1+z) : 1 - 1/(1+z)
//   bce = max(l,0) - l*t + log(1+z)
//   (1-p_t) = p + t - 2pt ; alpha_t = 0.75 - 0.5t
// ---------------------------------------------------------------------------
__device__ __forceinline__ void edge_body(float l, float t, int s, int d,
                                          float& fsum) {
    float z = __expf(-fabsf(l));
    float r = __fdividef(1.0f, 1.0f + z);     // MUFU.RCP path
    float p = (l >= 0.0f) ? r : (1.0f - r);
    float bce = fmaxf(l, 0.0f) - l * t + __logf(1.0f + z);
    float ompt = p + t - 2.0f * p * t;
    float at   = 0.75f - 0.5f * t;
    fsum = fmaf(at * ompt * ompt, bce, fsum);
    atomicAdd(&g_out_sums[s], p);
    atomicAdd(&g_in_sums[d], p);
}

__global__ void __launch_bounds__(256)
edge_kernel(const float* __restrict__ ep, const float* __restrict__ ye,
            const void* __restrict__ ei, int E) {
    __shared__ float sh[32];
    float fsum = 0.0f;
    const int tid    = blockIdx.x * blockDim.x + threadIdx.x;
    const int stride = gridDim.x * blockDim.x;

    int base = tid * 4;

    if (g_idx64 == 0) {
        const int* __restrict__ src = (const int*)ei;
        const int* __restrict__ dst = src + E;
        for (; base + 3 < E; base += stride * 4) {
            float4 l4 = *reinterpret_cast<const float4*>(ep + base);
            float4 t4 = *reinterpret_cast<const float4*>(ye + base);
            int4   s4 = *reinterpret_cast<const int4*>(src + base);
            int4   d4 = *reinterpret_cast<const int4*>(dst + base);
            edge_body(l4.x, t4.x, s4.x, d4.x, fsum);
            edge_body(l4.y, t4.y, s4.y, d4.y, fsum);
            edge_body(l4.z, t4.z, s4.z, d4.z, fsum);
            edge_body(l4.w, t4.w, s4.w, d4.w, fsum);
        }
        for (int i = base; i < E && i < base + 4; i++)
            edge_body(ep[i], ye[i], src[i], dst[i], fsum);
    } else {
        const long long* __restrict__ src = (const long long*)ei;
        const long long* __restrict__ dst = src + E;
        for (; base + 3 < E; base += stride * 4) {
            float4    l4  = *reinterpret_cast<const float4*>(ep + base);
            float4    t4  = *reinterpret_cast<const float4*>(ye + base);
            longlong2 s01 = *reinterpret_cast<const longlong2*>(src + base);
            longlong2 s23 = *reinterpret_cast<const longlong2*>(src + base + 2);
            longlong2 d01 = *reinterpret_cast<const longlong2*>(dst + base);
            longlong2 d23 = *reinterpret_cast<const longlong2*>(dst + base + 2);
            edge_body(l4.x, t4.x, (int)s01.x, (int)d01.x, fsum);
            edge_body(l4.y, t4.y, (int)s01.y, (int)d01.y, fsum);
            edge_body(l4.z, t4.z, (int)s23.x, (int)d23.x, fsum);
            edge_body(l4.w, t4.w, (int)s23.y, (int)d23.y, fsum);
        }
        for (int i = base; i < E && i < base + 4; i++)
            edge_body(ep[i], ye[i], (int)src[i], (int)dst[i], fsum);
    }

    float bsum = block_reduce_sum(fsum, sh);
    if (threadIdx.x == 0) g_edge_partial[blockIdx.x] = bsum;   // plain store
}

// ---------------------------------------------------------------------------
// Kernel 3: node pass (5 fused reductions, per-block partial stores)
//           + last-block finalize (no extra launch, no same-address atomics)
// ---------------------------------------------------------------------------
__global__ void __launch_bounds__(256)
node_kernel(const float* __restrict__ node_pred,
            const float* __restrict__ x,
            const float* __restrict__ y_nodes,
            const float* __restrict__ capacity,
            float* __restrict__ out,
            int N, int E) {
    __shared__ double shd[32];
    __shared__ float  shf[32];
    __shared__ bool   is_last;

    float cov = 0.0f, tour = 0.0f, dem = 0.0f, sq = 0.0f, cnt = 0.0f;

    for (int i = blockIdx.x * blockDim.x + threadIdx.x; i < N;
         i += gridDim.x * blockDim.x) {
        float ins  = g_in_sums[i];
        float outs = g_out_sums[i];
        float diff = ins - outs;
        tour += diff * diff;
        if (i > 0) {
            float a = ins - 1.0f, b = outs - 1.0f;
            cov += a * a + b * b;
            dem += x[i * 4 + 2];
        }
        float y = y_nodes[i];
        float m = (y >= 0.0f) ? 1.0f : 0.0f;
        float e = node_pred[i] - y;
        sq  += m * e * e;
        cnt += m;
    }

    float v;
    v = block_reduce_sum(cov,  shf); if (threadIdx.x == 0) g_node_partial[blockIdx.x * 5 + 0] = (double)v;
    v = block_reduce_sum(tour, shf); if (threadIdx.x == 0) g_node_partial[blockIdx.x * 5 + 1] = (double)v;
    v = block_reduce_sum(dem,  shf); if (threadIdx.x == 0) g_node_partial[blockIdx.x * 5 + 2] = (double)v;
    v = block_reduce_sum(sq,   shf); if (threadIdx.x == 0) g_node_partial[blockIdx.x * 5 + 3] = (double)v;
    v = block_reduce_sum(cnt,  shf); if (threadIdx.x == 0) g_node_partial[blockIdx.x * 5 + 4] = (double)v;

    if (threadIdx.x == 0) {
        __threadfence();
        unsigned t = atomicAdd(&g_done, 1u);
        is_last = (t == (unsigned)(gridDim.x - 1));
    }
    __syncthreads();
    if (!is_last) return;

    // ---- last block: final reduction + scalar combine ----
    const int tid = threadIdx.x;

    double acc[5];
    #pragma unroll
    for (int q = 0; q < 5; q++) {
        double s = 0.0;
        for (int b = tid; b < NODE_BLOCKS; b += blockDim.x)
            s += g_node_partial[b * 5 + q];
        acc[q] = block_reduce_sum_d(s, shd);
    }
    double fs = 0.0;
    for (int b = tid; b < EDGE_BLOCKS; b += blockDim.x)
        fs += (double)g_edge_partial[b];
    double focal_sum = block_reduce_sum_d(fs, shd);

    if (tid == 0) {
        double coverage  = acc[0] / (2.0 * (double)((N - 1) > 1 ? (N - 1) : 1));
        double tour_t    = acc[1] / (double)N;
        double in0  = (double)g_in_sums[0];
        double out0 = (double)g_out_sums[0];
        double depot = (in0 - out0) * (in0 - out0);
        double cap_value = (double)capacity[0];   // mean of 1 element
        double expected_tours = ceil(acc[2] / cap_value);
        double capacity_tours = (out0 - expected_tours) * (out0 - expected_tours);
        double similarity = focal_sum / (double)E;
        double node_loss  = acc[3] / fmax(acc[4], 1.0);
        double total = coverage * 5.0 + tour_t * 3.0 + depot * 2.0 +
                       capacity_tours * 1.5 + similarity * 0.3 + node_loss * 0.1;
        out[0] = (float)total;
    }
}

// ---------------------------------------------------------------------------
// kernel_launch
// Inputs (metadata order):
//   0: edge_predictions f32 [E]     4: y_edges    f32 [E]
//   1: node_predictions f32 [N]     5: y_nodes    f32 [N]
//   2: x                f32 [N,4]   6: edge_index [2,E] (i32/i64 auto-detected)
//   3: capacity         f32 [1]     7: num_nodes  (ignored; N = in_sizes[1])
// ---------------------------------------------------------------------------
extern "C" void kernel_launch(void* const* d_in, const int* in_sizes, int n_in,
                              void* d_out, int out_size) {
    const float* ep  = (const float*)d_in[0];
    const float* npr = (const float*)d_in[1];
    const float* x   = (const float*)d_in[2];
    const float* cap = (const float*)d_in[3];
    const float* ye  = (const float*)d_in[4];
    const float* yn  = (const float*)d_in[5];
    const void*  ei  = d_in[6];

    const int E = in_sizes[0];
    const int N = in_sizes[1];

    float* out = (float*)d_out;

    // 1. zero scratch + detect dtype + reset counter
    {
        int n4 = (N + 3) / 4;
        int blocks = (n4 + 255) / 256;
        zero_kernel<<<blocks, 256>>>((const int*)ei, n4);
    }
    // 2. edge pass (single persistent wave, 4 edges/thread/iter)
    edge_kernel<<<EDGE_BLOCKS, 256>>>(ep, ye, ei, E);
    // 3. node pass + fused finalize
    node_kernel<<<NODE_BLOCKS, 256>>>(npr, x, yn, cap, out, N, E);
}

// round 4
// speedup vs baseline: 1.0698x; 1.0698x over previous
#include <cuda_runtime.h>
#include <math.h>

// ---------------------------------------------------------------------------
// Scratch (allocation-free rule: __device__ globals; zero-init at module load)
// ---------------------------------------------------------------------------
#define MAXN        131072
#define EDGE_BLOCKS 2368      // 2 waves of 8 blocks/SM on 148 SMs (proven R2 config)
#define NODE_TPB    256

__device__ float        g_in_sums[MAXN];          // zero at load; node_kernel re-zeroes
__device__ float        g_out_sums[MAXN];
__device__ float        g_edge_partial[EDGE_BLOCKS];
__device__ double       g_node_partial[512 * 5];  // cov,tour,dem,sq,cnt per block
__device__ float        g_depot_in, g_depot_out;
__device__ unsigned int g_done;                   // zero at load; last block resets

// ---------------------------------------------------------------------------
// Block reductions (warp shuffle + shared)
// ---------------------------------------------------------------------------
__device__ __forceinline__ float block_reduce_sum(float v, float* sh) {
    const int lane = threadIdx.x & 31;
    const int wid  = threadIdx.x >> 5;
    #pragma unroll
    for (int o = 16; o > 0; o >>= 1) v += __shfl_down_sync(0xffffffffu, v, o);
    if (lane == 0) sh[wid] = v;
    __syncthreads();
    v = (threadIdx.x < (blockDim.x >> 5)) ? sh[threadIdx.x] : 0.0f;
    if (wid == 0) {
        #pragma unroll
        for (int o = 16; o > 0; o >>= 1) v += __shfl_down_sync(0xffffffffu, v, o);
    }
    __syncthreads();
    return v;   // valid in thread 0
}

__device__ __forceinline__ double block_reduce_sum_d(double v, double* sh) {
    const int lane = threadIdx.x & 31;
    const int wid  = threadIdx.x >> 5;
    #pragma unroll
    for (int o = 16; o > 0; o >>= 1) v += __shfl_down_sync(0xffffffffu, v, o);
    if (lane == 0) sh[wid] = v;
    __syncthreads();
    v = (threadIdx.x < (blockDim.x >> 5)) ? sh[threadIdx.x] : 0.0;
    if (wid == 0) {
        #pragma unroll
        for (int o = 16; o > 0; o >>= 1) v += __shfl_down_sync(0xffffffffu, v, o);
    }
    __syncthreads();
    return v;   // valid in thread 0
}

// ---------------------------------------------------------------------------
// Kernel 1: edge pass
//   p = sigmoid(l) scattered into in/out segment sums (2 float RED / edge)
//   focal loss partial -> per-block plain store
//   z = exp(-|l|); p = (l>=0) ? 1/(1+z) : 1 - 1/(1+z)
//   bce = max(l,0) - l*t + log(1+z)
//   (1-p_t) = p + t - 2pt ; alpha_t = 0.75 - 0.5t
// Index dtype detected per-block: int64 indices < 2^31 have zero high words;
// an int32 buffer has random indices in those slots (P[32 zeros] ~ 1e-160).
// ---------------------------------------------------------------------------
__device__ __forceinline__ void edge_body(float l, float t, int s, int d,
                                          float& fsum) {
    float z = __expf(-fabsf(l));
    float r = __fdividef(1.0f, 1.0f + z);
    float p = (l >= 0.0f) ? r : (1.0f - r);
    float bce = fmaxf(l, 0.0f) - l * t + __logf(1.0f + z);
    float ompt = p + t - 2.0f * p * t;
    float at   = 0.75f - 0.5f * t;
    fsum = fmaf(at * ompt * ompt, bce, fsum);
    atomicAdd(&g_out_sums[s], p);
    atomicAdd(&g_in_sums[d], p);
}

__global__ void __launch_bounds__(256)
edge_kernel(const float* __restrict__ ep, const float* __restrict__ ye,
            const void* __restrict__ ei, int E) {
    __shared__ float sh[32];
    __shared__ int   sh_is64;

    if (threadIdx.x == 0) {
        const int* w = (const int*)ei;
        int all_hi_zero = 1;
        #pragma unroll
        for (int k = 0; k < 32; k++)
            if (w[2 * k + 1] != 0) { all_hi_zero = 0; break; }
        sh_is64 = all_hi_zero;
    }
    __syncthreads();
    const bool is64 = (sh_is64 != 0);

    float fsum = 0.0f;
    const int tid    = blockIdx.x * blockDim.x + threadIdx.x;
    const int stride = gridDim.x * blockDim.x;

    int base = tid * 4;

    if (!is64) {
        const int* __restrict__ src = (const int*)ei;
        const int* __restrict__ dst = src + E;
        for (; base + 3 < E; base += stride * 4) {
            float4 l4 = *reinterpret_cast<const float4*>(ep + base);
            float4 t4 = *reinterpret_cast<const float4*>(ye + base);
            int4   s4 = *reinterpret_cast<const int4*>(src + base);
            int4   d4 = *reinterpret_cast<const int4*>(dst + base);
            edge_body(l4.x, t4.x, s4.x, d4.x, fsum);
            edge_body(l4.y, t4.y, s4.y, d4.y, fsum);
            edge_body(l4.z, t4.z, s4.z, d4.z, fsum);
            edge_body(l4.w, t4.w, s4.w, d4.w, fsum);
        }
        for (int i = base; i < E && i < base + 4; i++)
            edge_body(ep[i], ye[i], src[i], dst[i], fsum);
    } else {
        const long long* __restrict__ src = (const long long*)ei;
        const long long* __restrict__ dst = src + E;
        for (; base + 3 < E; base += stride * 4) {
            float4    l4  = *reinterpret_cast<const float4*>(ep + base);
            float4    t4  = *reinterpret_cast<const float4*>(ye + base);
            longlong2 s01 = *reinterpret_cast<const longlong2*>(src + base);
            longlong2 s23 = *reinterpret_cast<const longlong2*>(src + base + 2);
            longlong2 d01 = *reinterpret_cast<const longlong2*>(dst + base);
            longlong2 d23 = *reinterpret_cast<const longlong2*>(dst + base + 2);
            edge_body(l4.x, t4.x, (int)s01.x, (int)d01.x, fsum);
            edge_body(l4.y, t4.y, (int)s01.y, (int)d01.y, fsum);
            edge_body(l4.z, t4.z, (int)s23.x, (int)d23.x, fsum);
            edge_body(l4.w, t4.w, (int)s23.y, (int)d23.y, fsum);
        }
        for (int i = base; i < E && i < base + 4; i++)
            edge_body(ep[i], ye[i], (int)src[i], (int)dst[i], fsum);
    }

    float bsum = block_reduce_sum(fsum, sh);
    if (threadIdx.x == 0) g_edge_partial[blockIdx.x] = bsum;   // plain store
}

// ---------------------------------------------------------------------------
// Kernel 2: node pass — one thread per node.
//   Reads in/out sums, RESTORES THEM TO ZERO for the next graph replay,
//   computes 5 fused reductions, last block finalizes + resets g_done.
// ---------------------------------------------------------------------------
__global__ void __launch_bounds__(NODE_TPB)
node_kernel(const float* __restrict__ node_pred,
            const float* __restrict__ x,
            const float* __restrict__ y_nodes,
            const float* __restrict__ capacity,
            float* __restrict__ out,
            int N, int E) {
    __shared__ double shd[32];
    __shared__ float  shf[32];
    __shared__ bool   is_last;

    const int i = blockIdx.x * blockDim.x + threadIdx.x;

    float cov = 0.0f, tour = 0.0f, dem = 0.0f, sq = 0.0f, cnt = 0.0f;

    if (i < N) {
        float ins  = g_in_sums[i];
        float outs = g_out_sums[i];
        g_in_sums[i]  = 0.0f;          // restore invariant for next replay
        g_out_sums[i] = 0.0f;
        float diff = ins - outs;
        tour = diff * diff;
        if (i > 0) {
            float a = ins - 1.0f, b = outs - 1.0f;
            cov = a * a + b * b;
            dem = x[i * 4 + 2];
        } else {
            g_depot_in  = ins;         // save depot values for finalize
            g_depot_out = outs;
        }
        float y = y_nodes[i];
        float m = (y >= 0.0f) ? 1.0f : 0.0f;
        float e = node_pred[i] - y;
        sq  = m * e * e;
        cnt = m;
    }

    float v;
    v = block_reduce_sum(cov,  shf); if (threadIdx.x == 0) g_node_partial[blockIdx.x * 5 + 0] = (double)v;
    v = block_reduce_sum(tour, shf); if (threadIdx.x == 0) g_node_partial[blockIdx.x * 5 + 1] = (double)v;
    v = block_reduce_sum(dem,  shf); if (threadIdx.x == 0) g_node_partial[blockIdx.x * 5 + 2] = (double)v;
    v = block_reduce_sum(sq,   shf); if (threadIdx.x == 0) g_node_partial[blockIdx.x * 5 + 3] = (double)v;
    v = block_reduce_sum(cnt,  shf); if (threadIdx.x == 0) g_node_partial[blockIdx.x * 5 + 4] = (double)v;

    if (threadIdx.x == 0) {
        __threadfence();
        unsigned t = atomicAdd(&g_done, 1u);
        is_last = (t == (unsigned)(gridDim.x - 1));
    }
    __syncthreads();
    if (!is_last) return;

    // ---- last block: final reduction + scalar combine ----
    const int tid    = threadIdx.x;
    const int nblk   = gridDim.x;

    double acc[5];
    #pragma unroll
    for (int q = 0; q < 5; q++) {
        double s = 0.0;
        for (int b = tid; b < nblk; b += blockDim.x)
            s += g_node_partial[b * 5 + q];
        acc[q] = block_reduce_sum_d(s, shd);
    }
    double fs = 0.0;
    for (int b = tid; b < EDGE_BLOCKS; b += blockDim.x)
        fs += (double)g_edge_partial[b];
    double focal_sum = block_reduce_sum_d(fs, shd);

    if (tid == 0) {
        double coverage  = acc[0] / (2.0 * (double)((N - 1) > 1 ? (N - 1) : 1));
        double tour_t    = acc[1] / (double)N;
        double in0  = (double)g_depot_in;
        double out0 = (double)g_depot_out;
        double depot = (in0 - out0) * (in0 - out0);
        double cap_value = (double)capacity[0];   // mean of 1 element
        double expected_tours = ceil(acc[2] / cap_value);
        double capacity_tours = (out0 - expected_tours) * (out0 - expected_tours);
        double similarity = focal_sum / (double)E;
        double node_loss  = acc[3] / fmax(acc[4], 1.0);
        double total = coverage * 5.0 + tour_t * 3.0 + depot * 2.0 +
                       capacity_tours * 1.5 + similarity * 0.3 + node_loss * 0.1;
        out[0] = (float)total;
        g_done = 0u;                   // reset for next replay
    }
}

// ---------------------------------------------------------------------------
// kernel_launch — 2 launches per call
// Inputs (metadata order):
//   0: edge_predictions f32 [E]     4: y_edges    f32 [E]
//   1: node_predictions f32 [N]     5: y_nodes    f32 [N]
//   2: x                f32 [N,4]   6: edge_index [2,E] (i32/i64 auto-detected)
//   3: capacity         f32 [1]     7: num_nodes  (ignored; N = in_sizes[1])
// ---------------------------------------------------------------------------
extern "C" void kernel_launch(void* const* d_in, const int* in_sizes, int n_in,
                              void* d_out, int out_size) {
    const float* ep  = (const float*)d_in[0];
    const float* npr = (const float*)d_in[1];
    const float* x   = (const float*)d_in[2];
    const float* cap = (const float*)d_in[3];
    const float* ye  = (const float*)d_in[4];
    const float* yn  = (const float*)d_in[5];
    const void*  ei  = d_in[6];

    const int E = in_sizes[0];
    const int N = in_sizes[1];

    float* out = (float*)d_out;

    // 1. edge pass (2368 blocks = 2 waves; detect dtype per block)
    edge_kernel<<<EDGE_BLOCKS, 256>>>(ep, ye, ei, E);
    // 2. node pass + re-zero + fused finalize
    {
        int blocks = (N + NODE_TPB - 1) / NODE_TPB;   // 391 for N=100000 (< 512)
        node_kernel<<<blocks, NODE_TPB>>>(npr, x, yn, cap, out, N, E);
    }
}